// round 10
// baseline (speedup 1.0000x reference)
#include <cuda_runtime.h>
#include <math.h>

// YoloLoss, fixed shape: input [32,255,76,76] f32, targets [32,20,5] f32, l int32.
// R10: 512-thread blocks (grid 272) — halves per-block target-prep/epilogue/atomic
// costs again (R9 lever). Keeps: warp-coop class BCE, division-free argmax, per-warp
// ballot pruning, early input loads, atomicMax scatter map. 4 cells/thread.

#define IN_H 76
#define IN_W 76
#define HW   (IN_H * IN_W)        // 5776
#define NT   20
#define NCLS 80
#define MAXB 512

// per-block partials: 0=n_obj, 1=loc_sum, 2=cls_sum, 3=conf_num, 4=conf_mask_sum
__device__ double g_part[MAXB][5];
__device__ unsigned g_count = 0;

__constant__ float c_anchors[18] = {12,16, 19,36, 40,28, 36,75, 76,55,
                                    72,146, 142,110, 192,243, 459,401};

__device__ __forceinline__ float warp_sum(float v) {
    #pragma unroll
    for (int o = 16; o; o >>= 1) v += __shfl_down_sync(0xffffffffu, v, o);
    return v;
}
__device__ __forceinline__ float bfly_min(float v) {
    #pragma unroll
    for (int o = 16; o; o >>= 1) v = fminf(v, __shfl_xor_sync(0xffffffffu, v, o));
    return v;
}
__device__ __forceinline__ float bfly_max(float v) {
    #pragma unroll
    for (int o = 16; o; o >>= 1) v = fmaxf(v, __shfl_xor_sync(0xffffffffu, v, o));
    return v;
}
__device__ __forceinline__ double warp_sumd(double v) {
    #pragma unroll
    for (int o = 16; o; o >>= 1) v += __shfl_down_sync(0xffffffffu, v, o);
    return v;
}
__device__ __forceinline__ float ftanh(float x) {
    float r;
    asm("tanh.approx.f32 %0, %1;" : "=f"(r) : "f"(x));
    return r;
}
__device__ __forceinline__ float fsig(float x) {      // 1 MUFU sigmoid
    return fmaf(0.5f, ftanh(0.5f * x), 0.5f);
}
// softplus(z) = -log(sigmoid(-z)); equals clipped-BCE term exactly for |z| < ~16
__device__ __forceinline__ float fsoftplus(float z) {
    return __logf(1.0f + __expf(z));
}

__global__ void __launch_bounds__(512, 2)
yolo_fused(const float* __restrict__ inp, const float* __restrict__ tgt,
           const int* __restrict__ lptr, float* __restrict__ out)
{
    __shared__ float4   s_mm[NT];        // minx, maxx, miny, maxy
    __shared__ float    s_area[NT];
    __shared__ float    s_cx[NT], s_cy[NT], s_w[NT], s_h[NT];
    __shared__ int      s_cls[NT];
    __shared__ int      s_map[2048];     // cell->target (-1 = none), atomicMax build
    __shared__ double   s_acc[5];
    __shared__ int      s_islast;

    const int b    = blockIdx.y;
    const int tid  = threadIdx.x;
    const int lane = tid & 31;
    const int base = blockIdx.x * 2048;

    const int m4  = base + tid * 4;              // first cell of quad
    const bool vld = (m4 < 3 * HW);
    const int k   = m4 / HW;                     // constant across quad
    const int rem = m4 - k * HW;
    const int j   = rem / IN_W;
    const int i0  = rem - j * IN_W;
    const size_t eoff = ((size_t)b * 255 + (size_t)k * 85) * HW + rem;

    // ---- issue input loads FIRST (overlap with target preprocessing) ----
    float4 xv, yv, wv, hv, cv;
    if (vld) {
        xv = *(const float4*)(inp + eoff + 0 * HW);
        yv = *(const float4*)(inp + eoff + 1 * HW);
        wv = *(const float4*)(inp + eoff + 2 * HW);
        hv = *(const float4*)(inp + eoff + 3 * HW);
        cv = *(const float4*)(inp + eoff + 4 * HW);
    }
    const int l  = __ldg(lptr);
    const int m0 = 6 - 3 * l;

    // map init (one int4 store per thread)
    ((int4*)s_map)[tid] = make_int4(-1, -1, -1, -1);
    if (tid < 5) s_acc[tid] = 0.0;

    // ---- target preprocessing (concurrent with in-flight input loads) ----
    if (tid < NT) {
        const float* tp = tgt + ((size_t)b * NT + tid) * 5;
        float gx = tp[0] * (float)IN_W;
        float gy = tp[1] * (float)IN_H;
        float gw = tp[2] * (float)IN_W;
        float gh = tp[3] * (float)IN_H;
        // argmax over 9 anchors, division-free: r_a > r_b <=> inter_a*uni_b > inter_b*uni_a
        float binter = 0.0f, buni = 1e-30f; int bn = 0;
        #pragma unroll
        for (int a = 0; a < 9; a++) {
            float aw = c_anchors[2*a] * 0.125f, ah = c_anchors[2*a+1] * 0.125f;
            float inter = fminf(gw, aw) * fminf(gh, ah);
            float uni   = gw * gh + aw * ah - inter;
            if (inter * buni > binter * uni) { binter = inter; buni = uni; bn = a; }
        }
        int kk = bn - m0;
        int gi = (int)floorf(gx); gi = min(max(gi, 0), IN_W - 1);
        int gj = (int)floorf(gy); gj = min(max(gj, 0), IN_H - 1);
        if (kk >= 0 && kk < 3) {
            int d = kk * HW + gj * IN_W + gi - base;
            if ((unsigned)d < 2048u) atomicMax(&s_map[d], tid);  // larger t wins = ref order
        }
        s_mm[tid] = make_float4(gx - gw * 0.5f, gx + gw * 0.5f,
                                gy - gh * 0.5f, gy + gh * 0.5f);
        s_area[tid] = gw * gh;
        s_cx[tid] = gx; s_cy[tid] = gy; s_w[tid] = gw; s_h[tid] = gh;
        s_cls[tid] = (int)tp[4];
    }

    // ---- decode (independent of shared; anchors from constant) ----
    float pnx[4], pxx[4], pny[4], pxy[4], pa[4];
    float cr[4];
    if (vld) {
        const float aw = c_anchors[2 * (m0 + k)]     * 0.125f;
        const float ah = c_anchors[2 * (m0 + k) + 1] * 0.125f;
        const float xr[4] = {xv.x, xv.y, xv.z, xv.w};
        const float yr[4] = {yv.x, yv.y, yv.z, yv.w};
        const float wr[4] = {wv.x, wv.y, wv.z, wv.w};
        const float hr[4] = {hv.x, hv.y, hv.z, hv.w};
        cr[0] = cv.x; cr[1] = cv.y; cr[2] = cv.z; cr[3] = cv.w;
        #pragma unroll
        for (int c = 0; c < 4; c++) {
            float px = (float)(i0 + c) + fsig(xr[c]);
            float py = (float)j        + fsig(yr[c]);
            float pw = __expf(wr[c]) * aw;
            float ph = __expf(hr[c]) * ah;
            pnx[c] = px - pw * 0.5f;  pxx[c] = px + pw * 0.5f;
            pny[c] = py - ph * 0.5f;  pxy[c] = py + ph * 0.5f;
            pa[c]  = pw * ph;
        }
    }

    // ---- per-warp bounds via butterflies (no smem, no extra sync) ----
    float pamin = 1e30f, pamax = -1e30f, pnymin = 1e30f, pxymax = -1e30f;
    if (vld) {
        #pragma unroll
        for (int c = 0; c < 4; c++) {
            pamin  = fminf(pamin,  pa[c]);  pamax  = fmaxf(pamax,  pa[c]);
            pnymin = fminf(pnymin, pny[c]); pxymax = fmaxf(pxymax, pxy[c]);
        }
    }
    const float wpamin  = bfly_min(pamin);
    const float wpamax  = bfly_max(pamax);
    const float wpnymin = bfly_min(pnymin);
    const float wpxymax = bfly_max(pxymax);

    __syncthreads();   // targets + map ready

    // ---- per-warp prune: lanes 0..19 test their target against warp bounds ----
    unsigned keepmsk;
    {
        bool keep = false;
        if (lane < NT) {
            float ar = s_area[lane];
            float4 mm = s_mm[lane];
            // trigger 3*inter-ar > pa needs ar/2 < pa < 2*ar (margined) and y-overlap
            keep = (wpamin < 2.0002f * ar) && (2.0002f * wpamax > ar)
                && (mm.w >= wpnymin) && (mm.z <= wpxymax);
        }
        keepmsk = __ballot_sync(0xffffffffu, keep);
    }

    float objf = 0.f, loc = 0.f, clsl = 0.f, confn = 0.f, cmask = 0.f;
    bool objc[4] = {false, false, false, false};

    if (vld) {
        // ignore loop over surviving targets (warp-uniform mask walk)
        float ignmax[4] = {-1e30f, -1e30f, -1e30f, -1e30f};
        unsigned msk = keepmsk;
        while (msk) {
            const int t = __ffs(msk) - 1;
            msk &= msk - 1;
            const float4 mm = s_mm[t];
            const float  ar = s_area[t];
            #pragma unroll
            for (int c = 0; c < 4; c++) {
                float iw = fminf(mm.y, pxx[c]) - fmaxf(mm.x, pnx[c]);
                float ih = fminf(mm.w, pxy[c]) - fmaxf(mm.z, pny[c]);
                float inter = fmaxf(iw, 0.f) * fmaxf(ih, 0.f);
                ignmax[c] = fmaxf(ignmax[c], fmaf(3.0f, inter, -ar));
            }
        }

        const int4 mi = ((const int4*)s_map)[tid];
        const int tq[4] = {mi.x, mi.y, mi.z, mi.w};

        #pragma unroll
        for (int c = 0; c < 4; c++) {
            const int t = tq[c];
            const bool isobj = (t >= 0);
            objc[c] = isobj;
            objf += isobj ? 1.0f : 0.0f;

            float cm = (isobj || ignmax[c] <= pa[c]) ? 1.0f : 0.0f;
            confn += cm * fsoftplus(isobj ? -cr[c] : cr[c]);
            cmask += cm;

            if (isobj) {   // rare: CIoU (class BCE handled cooperatively below)
                float pw = pxx[c] - pnx[c];
                float ph = pxy[c] - pny[c];
                float px = 0.5f * (pnx[c] + pxx[c]);
                float py = 0.5f * (pny[c] + pxy[c]);
                float gx = s_cx[t], gy = s_cy[t], gw = s_w[t], gh = s_h[t];
                float g_minx = gx - gw*0.5f, g_maxx = gx + gw*0.5f;
                float g_miny = gy - gh*0.5f, g_maxy = gy + gh*0.5f;
                float iw = fmaxf(fminf(g_maxx, pxx[c]) - fmaxf(g_minx, pnx[c]), 0.f);
                float ih = fmaxf(fminf(g_maxy, pxy[c]) - fmaxf(g_miny, pny[c]), 0.f);
                float inter = iw * ih;
                float uni   = fmaxf(pa[c] + gw * gh - inter, 1e-6f);
                float iou   = inter / uni;
                float dx = px - gx, dy = py - gy;
                float cd = dx * dx + dy * dy;
                float ew = fmaxf(fmaxf(g_maxx, pxx[c]) - fminf(g_minx, pnx[c]), 0.f);
                float eh = fmaxf(fmaxf(g_maxy, pxy[c]) - fminf(g_miny, pny[c]), 0.f);
                float ed = fmaxf(ew * ew + eh * eh, 1e-6f);
                float da = atanf(pw / fmaxf(ph, 1e-6f))
                         - atanf(gw / fmaxf(gh, 1e-6f));
                float v  = 0.405284734569351f * da * da;  // 4/pi^2
                float alpha = v / fmaxf(1.0f - iou + v, 1e-6f);
                loc += 1.0f - (iou - cd / ed - alpha * v);
            }
        }
    }

    // ---- warp-cooperative class BCE over obj cells (32 lanes split 80 ch) ----
    #pragma unroll
    for (int c = 0; c < 4; c++) {
        unsigned msk = __ballot_sync(0xffffffffu, vld && objc[c]);
        while (msk) {
            const int src = __ffs(msk) - 1;
            msk &= msk - 1;
            const int cell = __shfl_sync(0xffffffffu, m4 + c, src);
            const int t    = s_map[cell - base];          // broadcast LDS
            const int cc   = s_cls[t];
            const int k2   = cell / HW;
            const int rem2 = cell - k2 * HW;
            const size_t off = ((size_t)b * 255 + (size_t)k2 * 85) * HW + rem2;
            float cs = 0.0f;
            #pragma unroll
            for (int q = 0; q < 3; q++) {
                int ch = lane + q * 32;
                if (ch < NCLS) {
                    float z = inp[off + (size_t)(5 + ch) * HW];
                    cs += fsoftplus((ch == cc) ? -z : z);
                }
            }
            cs = warp_sum(cs);
            if (lane == 0) clsl += cs;
        }
    }

    // block reduction
    float vals[5] = {objf, loc, clsl, confn, cmask};
    #pragma unroll
    for (int q = 0; q < 5; q++) {
        float v = warp_sum(vals[q]);
        if (lane == 0 && v != 0.0f) atomicAdd(&s_acc[q], (double)v);
    }
    __syncthreads();

    const int nblocks = gridDim.x * gridDim.y;
    const int bid = blockIdx.y * gridDim.x + blockIdx.x;
    if (tid < 5) g_part[bid][tid] = s_acc[tid];

    if (tid == 0) {
        __threadfence();
        unsigned v = atomicAdd(&g_count, 1u);
        s_islast = (v == (unsigned)(nblocks - 1));
        if (s_islast) g_count = 0;    // self-reset -> graph-replay deterministic
    }
    __syncthreads();
    if (!s_islast) return;

    double acc[5] = {0, 0, 0, 0, 0};
    for (int r = tid; r < nblocks; r += blockDim.x) {
        #pragma unroll
        for (int q = 0; q < 5; q++) acc[q] += g_part[r][q];
    }
    __shared__ double s_fin[5];
    if (tid < 5) s_fin[tid] = 0.0;
    __syncthreads();
    #pragma unroll
    for (int q = 0; q < 5; q++) {
        double v = warp_sumd(acc[q]);
        if (lane == 0 && v != 0.0) atomicAdd(&s_fin[q], v);
    }
    __syncthreads();
    if (tid == 0) {
        double n_obj = s_fin[0] < 1.0 ? 1.0 : s_fin[0];
        double cms   = s_fin[4] < 1.0 ? 1.0 : s_fin[4];
        const double balance = (l == 0) ? 0.4 : (l == 1 ? 1.0 : 4.0);
        const double obj_ratio = 5.0 * 608.0 * 608.0 / (416.0 * 416.0);
        double loss = s_fin[1] / n_obj * 0.05
                    + s_fin[3] / cms * balance * obj_ratio
                    + s_fin[2] / (n_obj * (double)NCLS);
        out[0] = (float)loss;
    }
}

extern "C" void kernel_launch(void* const* d_in, const int* in_sizes, int n_in,
                              void* d_out, int out_size)
{
    const float* inp  = (const float*)d_in[0];
    const float* tgt  = (const float*)d_in[1];
    const int*   lptr = (const int*)d_in[2];
    float* out = (float*)d_out;

    const int bs = in_sizes[0] / (255 * HW);        // 32
    const int blocks_x = (3 * HW / 4 + 511) / 512;  // 9 (9*2048 >= 17328)

    yolo_fused<<<dim3(blocks_x, bs), 512>>>(inp, tgt, lptr, out);
}

// round 11
// speedup vs baseline: 1.1409x; 1.1409x over previous
#include <cuda_runtime.h>
#include <math.h>

// YoloLoss, fixed shape: input [32,255,76,76] f32, targets [32,20,5] f32, l int32.
// R11 (on R9 shape: 256 thr, grid 544): lazy x/y decode. Prune targets using only
// exp(w),exp(h)-derived bounds (py in (j,j+1) a priori); warps with no surviving
// targets AND no obj cells skip the x/y loads + sigmoid decode + ignore loop
// entirely (cm=1 there). ~90% of warps take the short path.

#define IN_H 76
#define IN_W 76
#define HW   (IN_H * IN_W)        // 5776
#define NT   20
#define NCLS 80
#define MAXB 1024

// per-block partials: 0=n_obj, 1=loc_sum, 2=cls_sum, 3=conf_num, 4=conf_mask_sum
__device__ double g_part[MAXB][5];
__device__ unsigned g_count = 0;

__constant__ float c_anchors[18] = {12,16, 19,36, 40,28, 36,75, 76,55,
                                    72,146, 142,110, 192,243, 459,401};

__device__ __forceinline__ float warp_sum(float v) {
    #pragma unroll
    for (int o = 16; o; o >>= 1) v += __shfl_down_sync(0xffffffffu, v, o);
    return v;
}
__device__ __forceinline__ float bfly_min(float v) {
    #pragma unroll
    for (int o = 16; o; o >>= 1) v = fminf(v, __shfl_xor_sync(0xffffffffu, v, o));
    return v;
}
__device__ __forceinline__ float bfly_max(float v) {
    #pragma unroll
    for (int o = 16; o; o >>= 1) v = fmaxf(v, __shfl_xor_sync(0xffffffffu, v, o));
    return v;
}
__device__ __forceinline__ double warp_sumd(double v) {
    #pragma unroll
    for (int o = 16; o; o >>= 1) v += __shfl_down_sync(0xffffffffu, v, o);
    return v;
}
__device__ __forceinline__ float ftanh(float x) {
    float r;
    asm("tanh.approx.f32 %0, %1;" : "=f"(r) : "f"(x));
    return r;
}
__device__ __forceinline__ float fsig(float x) {      // 1 MUFU sigmoid
    return fmaf(0.5f, ftanh(0.5f * x), 0.5f);
}
// softplus(z) = -log(sigmoid(-z)); equals clipped-BCE term exactly for |z| < ~16
__device__ __forceinline__ float fsoftplus(float z) {
    return __logf(1.0f + __expf(z));
}

__global__ void __launch_bounds__(256, 4)
yolo_fused(const float* __restrict__ inp, const float* __restrict__ tgt,
           const int* __restrict__ lptr, float* __restrict__ out)
{
    __shared__ float4   s_mm[NT];        // minx, maxx, miny, maxy
    __shared__ float    s_area[NT];
    __shared__ float    s_cx[NT], s_cy[NT], s_w[NT], s_h[NT];
    __shared__ int      s_cls[NT];
    __shared__ int      s_map[1024];     // cell->target (-1 = none), atomicMax build
    __shared__ double   s_acc[5];
    __shared__ int      s_islast;

    const int b    = blockIdx.y;
    const int tid  = threadIdx.x;
    const int lane = tid & 31;
    const int base = blockIdx.x * 1024;

    const int m4  = base + tid * 4;              // first cell of quad
    const bool vld = (m4 < 3 * HW);
    const int k   = m4 / HW;                     // constant across quad
    const int rem = m4 - k * HW;
    const int j   = rem / IN_W;
    const int i0  = rem - j * IN_W;
    const size_t eoff = ((size_t)b * 255 + (size_t)k * 85) * HW + rem;

    // ---- issue w/h/conf loads FIRST (x/y deferred; overlap with target prep) ----
    float4 wv, hv, cv;
    if (vld) {
        wv = *(const float4*)(inp + eoff + 2 * HW);
        hv = *(const float4*)(inp + eoff + 3 * HW);
        cv = *(const float4*)(inp + eoff + 4 * HW);
    }
    const int l  = __ldg(lptr);
    const int m0 = 6 - 3 * l;

    // map init
    s_map[tid] = -1; s_map[tid + 256] = -1; s_map[tid + 512] = -1; s_map[tid + 768] = -1;
    if (tid < 5) s_acc[tid] = 0.0;

    // ---- target preprocessing (concurrent with in-flight loads) ----
    if (tid < NT) {
        const float* tp = tgt + ((size_t)b * NT + tid) * 5;
        float gx = tp[0] * (float)IN_W;
        float gy = tp[1] * (float)IN_H;
        float gw = tp[2] * (float)IN_W;
        float gh = tp[3] * (float)IN_H;
        // argmax over 9 anchors, division-free
        float binter = 0.0f, buni = 1e-30f; int bn = 0;
        #pragma unroll
        for (int a = 0; a < 9; a++) {
            float aw = c_anchors[2*a] * 0.125f, ah = c_anchors[2*a+1] * 0.125f;
            float inter = fminf(gw, aw) * fminf(gh, ah);
            float uni   = gw * gh + aw * ah - inter;
            if (inter * buni > binter * uni) { binter = inter; buni = uni; bn = a; }
        }
        int kk = bn - m0;
        int gi = (int)floorf(gx); gi = min(max(gi, 0), IN_W - 1);
        int gj = (int)floorf(gy); gj = min(max(gj, 0), IN_H - 1);
        if (kk >= 0 && kk < 3) {
            int d = kk * HW + gj * IN_W + gi - base;
            if ((unsigned)d < 1024u) atomicMax(&s_map[d], tid);  // larger t wins = ref order
        }
        s_mm[tid] = make_float4(gx - gw * 0.5f, gx + gw * 0.5f,
                                gy - gh * 0.5f, gy + gh * 0.5f);
        s_area[tid] = gw * gh;
        s_cx[tid] = gx; s_cy[tid] = gy; s_w[tid] = gw; s_h[tid] = gh;
        s_cls[tid] = (int)tp[4];
    }

    // ---- cheap decode: pw/ph/pa only (2 MUFU per cell) ----
    const float aw = c_anchors[2 * (m0 + k)]     * 0.125f;
    const float ah = c_anchors[2 * (m0 + k) + 1] * 0.125f;
    float pw[4], ph[4], pa[4], cr[4];
    if (vld) {
        const float wr[4] = {wv.x, wv.y, wv.z, wv.w};
        const float hr[4] = {hv.x, hv.y, hv.z, hv.w};
        cr[0] = cv.x; cr[1] = cv.y; cr[2] = cv.z; cr[3] = cv.w;
        #pragma unroll
        for (int c = 0; c < 4; c++) {
            pw[c] = __expf(wr[c]) * aw;
            ph[c] = __expf(hr[c]) * ah;
            pa[c] = pw[c] * ph[c];
        }
    }

    // ---- warp bounds (no centers needed: py in (j, j+1)) ----
    float pamin = 1e30f, pamax = -1e30f, phmax = 0.0f;
    float jminf = 1e30f, jmaxf = -1e30f;
    if (vld) {
        #pragma unroll
        for (int c = 0; c < 4; c++) {
            pamin = fminf(pamin, pa[c]); pamax = fmaxf(pamax, pa[c]);
            phmax = fmaxf(phmax, ph[c]);
        }
        jminf = (float)j; jmaxf = (float)j;
    }
    const float wpamin = bfly_min(pamin);
    const float wpamax = bfly_max(pamax);
    const float wphmax = bfly_max(phmax);
    const float wjmin  = bfly_min(jminf);
    const float wjmax  = bfly_max(jmaxf);

    __syncthreads();   // targets + map ready

    // ---- per-warp prune (conservative bounds; tiny margins cover rounding) ----
    unsigned keepmsk;
    {
        bool keep = false;
        if (lane < NT) {
            float ar = s_area[lane];
            float4 mm = s_mm[lane];
            // trigger 3*inter-ar > pa needs ar/2 < pa < 2*ar; y-overlap with
            // pny > jmin - phmax/2 and pxy < jmax+1 + phmax/2
            keep = (wpamin < 2.0002f * ar) && (2.0002f * wpamax > ar)
                && (mm.w >= wjmin - 0.5f * wphmax - 1e-3f)
                && (mm.z <= wjmax + 1.0f + 0.5f * wphmax + 1e-3f);
        }
        keepmsk = __ballot_sync(0xffffffffu, keep);
    }

    // obj map for the quad
    const int4 mi = ((const int4*)s_map)[tid];
    const int tq[4] = {mi.x, mi.y, mi.z, mi.w};
    const bool anyobj_lane = vld && ((tq[0] | tq[1] | tq[2] | tq[3]) >= 0) ? true : false;
    const unsigned objwmsk = __ballot_sync(0xffffffffu, anyobj_lane);
    const bool need_xy = (keepmsk != 0u) || (objwmsk != 0u);   // warp-uniform

    float objf = 0.f, loc = 0.f, clsl = 0.f, confn = 0.f, cmask = 0.f;
    bool objc[4] = {false, false, false, false};

    if (!need_xy) {
        // short path: no surviving targets, no obj cells -> cm=1, bce=softplus(cr)
        if (vld) {
            #pragma unroll
            for (int c = 0; c < 4; c++) confn += fsoftplus(cr[c]);
            cmask = 4.0f;
        }
    } else {
        // full path: load x/y, decode corners, ignore loop, obj handling
        float pnx[4], pxx[4], pny[4], pxy[4];
        if (vld) {
            const float4 xv = *(const float4*)(inp + eoff + 0 * HW);
            const float4 yv = *(const float4*)(inp + eoff + 1 * HW);
            const float xr[4] = {xv.x, xv.y, xv.z, xv.w};
            const float yr[4] = {yv.x, yv.y, yv.z, yv.w};
            #pragma unroll
            for (int c = 0; c < 4; c++) {
                float px = (float)(i0 + c) + fsig(xr[c]);
                float py = (float)j        + fsig(yr[c]);
                pnx[c] = px - pw[c] * 0.5f;  pxx[c] = px + pw[c] * 0.5f;
                pny[c] = py - ph[c] * 0.5f;  pxy[c] = py + ph[c] * 0.5f;
            }
        }

        if (vld) {
            float ignmax[4] = {-1e30f, -1e30f, -1e30f, -1e30f};
            unsigned msk = keepmsk;
            while (msk) {
                const int t = __ffs(msk) - 1;
                msk &= msk - 1;
                const float4 mm = s_mm[t];
                const float  ar = s_area[t];
                #pragma unroll
                for (int c = 0; c < 4; c++) {
                    float iw = fminf(mm.y, pxx[c]) - fmaxf(mm.x, pnx[c]);
                    float ih = fminf(mm.w, pxy[c]) - fmaxf(mm.z, pny[c]);
                    float inter = fmaxf(iw, 0.f) * fmaxf(ih, 0.f);
                    ignmax[c] = fmaxf(ignmax[c], fmaf(3.0f, inter, -ar));
                }
            }

            #pragma unroll
            for (int c = 0; c < 4; c++) {
                const int t = tq[c];
                const bool isobj = (t >= 0);
                objc[c] = isobj;
                objf += isobj ? 1.0f : 0.0f;

                float cm = (isobj || ignmax[c] <= pa[c]) ? 1.0f : 0.0f;
                confn += cm * fsoftplus(isobj ? -cr[c] : cr[c]);
                cmask += cm;

                if (isobj) {   // rare: CIoU (class BCE handled cooperatively below)
                    float px = 0.5f * (pnx[c] + pxx[c]);
                    float py = 0.5f * (pny[c] + pxy[c]);
                    float gx = s_cx[t], gy = s_cy[t], gw = s_w[t], gh = s_h[t];
                    float g_minx = gx - gw*0.5f, g_maxx = gx + gw*0.5f;
                    float g_miny = gy - gh*0.5f, g_maxy = gy + gh*0.5f;
                    float iw = fmaxf(fminf(g_maxx, pxx[c]) - fmaxf(g_minx, pnx[c]), 0.f);
                    float ih = fmaxf(fminf(g_maxy, pxy[c]) - fmaxf(g_miny, pny[c]), 0.f);
                    float inter = iw * ih;
                    float uni   = fmaxf(pa[c] + gw * gh - inter, 1e-6f);
                    float iou   = inter / uni;
                    float dx = px - gx, dy = py - gy;
                    float cd = dx * dx + dy * dy;
                    float ew = fmaxf(fmaxf(g_maxx, pxx[c]) - fminf(g_minx, pnx[c]), 0.f);
                    float eh = fmaxf(fmaxf(g_maxy, pxy[c]) - fminf(g_miny, pny[c]), 0.f);
                    float ed = fmaxf(ew * ew + eh * eh, 1e-6f);
                    float da = atanf(pw[c] / fmaxf(ph[c], 1e-6f))
                             - atanf(gw / fmaxf(gh, 1e-6f));
                    float v  = 0.405284734569351f * da * da;  // 4/pi^2
                    float alpha = v / fmaxf(1.0f - iou + v, 1e-6f);
                    loc += 1.0f - (iou - cd / ed - alpha * v);
                }
            }
        }

        // warp-cooperative class BCE over obj cells (32 lanes split 80 ch)
        #pragma unroll
        for (int c = 0; c < 4; c++) {
            unsigned msk = __ballot_sync(0xffffffffu, vld && objc[c]);
            while (msk) {
                const int src = __ffs(msk) - 1;
                msk &= msk - 1;
                const int cell = __shfl_sync(0xffffffffu, m4 + c, src);
                const int t    = s_map[cell - base];
                const int cc   = s_cls[t];
                const int k2   = cell / HW;
                const int rem2 = cell - k2 * HW;
                const size_t off = ((size_t)b * 255 + (size_t)k2 * 85) * HW + rem2;
                float cs = 0.0f;
                #pragma unroll
                for (int q = 0; q < 3; q++) {
                    int ch = lane + q * 32;
                    if (ch < NCLS) {
                        float z = inp[off + (size_t)(5 + ch) * HW];
                        cs += fsoftplus((ch == cc) ? -z : z);
                    }
                }
                cs = warp_sum(cs);
                if (lane == 0) clsl += cs;
            }
        }
    }

    // block reduction
    float vals[5] = {objf, loc, clsl, confn, cmask};
    #pragma unroll
    for (int q = 0; q < 5; q++) {
        float v = warp_sum(vals[q]);
        if (lane == 0 && v != 0.0f) atomicAdd(&s_acc[q], (double)v);
    }
    __syncthreads();

    const int nblocks = gridDim.x * gridDim.y;
    const int bid = blockIdx.y * gridDim.x + blockIdx.x;
    if (tid < 5) g_part[bid][tid] = s_acc[tid];

    if (tid == 0) {
        __threadfence();
        unsigned v = atomicAdd(&g_count, 1u);
        s_islast = (v == (unsigned)(nblocks - 1));
        if (s_islast) g_count = 0;    // self-reset -> graph-replay deterministic
    }
    __syncthreads();
    if (!s_islast) return;

    double acc[5] = {0, 0, 0, 0, 0};
    for (int r = tid; r < nblocks; r += blockDim.x) {
        #pragma unroll
        for (int q = 0; q < 5; q++) acc[q] += g_part[r][q];
    }
    __shared__ double s_fin[5];
    if (tid < 5) s_fin[tid] = 0.0;
    __syncthreads();
    #pragma unroll
    for (int q = 0; q < 5; q++) {
        double v = warp_sumd(acc[q]);
        if (lane == 0 && v != 0.0) atomicAdd(&s_fin[q], v);
    }
    __syncthreads();
    if (tid == 0) {
        double n_obj = s_fin[0] < 1.0 ? 1.0 : s_fin[0];
        double cms   = s_fin[4] < 1.0 ? 1.0 : s_fin[4];
        const double balance = (l == 0) ? 0.4 : (l == 1 ? 1.0 : 4.0);
        const double obj_ratio = 5.0 * 608.0 * 608.0 / (416.0 * 416.0);
        double loss = s_fin[1] / n_obj * 0.05
                    + s_fin[3] / cms * balance * obj_ratio
                    + s_fin[2] / (n_obj * (double)NCLS);
        out[0] = (float)loss;
    }
}

extern "C" void kernel_launch(void* const* d_in, const int* in_sizes, int n_in,
                              void* d_out, int out_size)
{
    const float* inp  = (const float*)d_in[0];
    const float* tgt  = (const float*)d_in[1];
    const int*   lptr = (const int*)d_in[2];
    float* out = (float*)d_out;

    const int bs = in_sizes[0] / (255 * HW);        // 32
    const int blocks_x = (3 * HW / 4 + 255) / 256;  // 17

    yolo_fused<<<dim3(blocks_x, bs), 256>>>(inp, tgt, lptr, out);
}

// round 14
// speedup vs baseline: 1.2448x; 1.0911x over previous
#include <cuda_runtime.h>
#include <math.h>

// YoloLoss, fixed shape: input [32,255,76,76] f32, targets [32,20,5] f32, l int32.
// R14 = R13 with the obj-guard bug fixed: (tm0|tm1|tm2|tm3)>=0 (bitwise OR of -1
// sentinels is always -1) -> logical OR of per-cell tests. Warp-autonomous:
// register-resident targets, shfl ignore loop, ballot obj-match, race-free
// per-warp-slot epilogue, zero pre-epilogue barriers.

#define IN_H 76
#define IN_W 76
#define HW   (IN_H * IN_W)        // 5776
#define NT   20
#define NCLS 80
#define MAXB 1024
#define NWARP 8

// per-block partials: 0=n_obj, 1=loc_sum, 2=cls_sum, 3=conf_num, 4=conf_mask_sum
__device__ double g_part[MAXB][5];
__device__ unsigned g_count = 0;

__constant__ float c_anchors[18] = {12,16, 19,36, 40,28, 36,75, 76,55,
                                    72,146, 142,110, 192,243, 459,401};

__device__ __forceinline__ float warp_sum(float v) {
    #pragma unroll
    for (int o = 16; o; o >>= 1) v += __shfl_down_sync(0xffffffffu, v, o);
    return v;
}
__device__ __forceinline__ float bfly_min(float v) {
    #pragma unroll
    for (int o = 16; o; o >>= 1) v = fminf(v, __shfl_xor_sync(0xffffffffu, v, o));
    return v;
}
__device__ __forceinline__ float bfly_max(float v) {
    #pragma unroll
    for (int o = 16; o; o >>= 1) v = fmaxf(v, __shfl_xor_sync(0xffffffffu, v, o));
    return v;
}
__device__ __forceinline__ double warp_sumd(double v) {
    #pragma unroll
    for (int o = 16; o; o >>= 1) v += __shfl_down_sync(0xffffffffu, v, o);
    return v;
}
__device__ __forceinline__ float ftanh(float x) {
    float r;
    asm("tanh.approx.f32 %0, %1;" : "=f"(r) : "f"(x));
    return r;
}
__device__ __forceinline__ float fsig(float x) {      // 1 MUFU sigmoid
    return fmaf(0.5f, ftanh(0.5f * x), 0.5f);
}
// softplus(z) = -log(sigmoid(-z)); equals clipped-BCE term exactly for |z| < ~16
__device__ __forceinline__ float fsoftplus(float z) {
    return __logf(1.0f + __expf(z));
}

__global__ void __launch_bounds__(256, 4)
yolo_fused(const float* __restrict__ inp, const float* __restrict__ tgt,
           const int* __restrict__ lptr, float* __restrict__ out)
{
    __shared__ float    s_wsum[NWARP][5];   // per-warp exclusive slots (race-free)
    __shared__ int      s_islast;

    const int b    = blockIdx.y;
    const int tid  = threadIdx.x;
    const int wid  = tid >> 5;
    const int lane = tid & 31;
    const int base = blockIdx.x * 1024;

    const int m4  = base + tid * 4;              // first cell of quad
    const bool vld = (m4 < 3 * HW);
    const int k   = min(m4 / HW, 2);             // clamp for tail quads
    const int rem = m4 - k * HW;
    const int j   = min(rem / IN_W, IN_H - 1);
    const int i0  = rem - j * IN_W;
    const size_t eoff = ((size_t)b * 255 + (size_t)k * 85) * HW + rem;

    // ---- eager input loads (MLP=5, overlap target prep) ----
    float4 xv = make_float4(0,0,0,0), yv = xv, wv = xv, hv = xv, cv = xv;
    if (vld) {
        xv = *(const float4*)(inp + eoff + 0 * HW);
        yv = *(const float4*)(inp + eoff + 1 * HW);
        wv = *(const float4*)(inp + eoff + 2 * HW);
        hv = *(const float4*)(inp + eoff + 3 * HW);
        cv = *(const float4*)(inp + eoff + 4 * HW);
    }
    const int l  = __ldg(lptr);
    const int m0 = 6 - 3 * l;

    // ---- register-resident targets: lane t owns target t ----
    float t_mmx = 0.f, t_mmy = 0.f, t_mmz = 0.f, t_mmw = 0.f, t_area = 1e30f;
    int   t_cell = -1, t_cls = 0;
    if (lane < NT) {
        const float* tp = tgt + ((size_t)b * NT + lane) * 5;
        float gx = tp[0] * (float)IN_W;
        float gy = tp[1] * (float)IN_H;
        float gw = tp[2] * (float)IN_W;
        float gh = tp[3] * (float)IN_H;
        // argmax over 9 anchors, division-free: r_a > r_b <=> inter_a*uni_b > inter_b*uni_a
        float binter = 0.0f, buni = 1e-30f; int bn = 0;
        #pragma unroll
        for (int a = 0; a < 9; a++) {
            float aw = c_anchors[2*a] * 0.125f, ah = c_anchors[2*a+1] * 0.125f;
            float inter = fminf(gw, aw) * fminf(gh, ah);
            float uni   = gw * gh + aw * ah - inter;
            if (inter * buni > binter * uni) { binter = inter; buni = uni; bn = a; }
        }
        int kk = bn - m0;
        int gi = (int)floorf(gx); gi = min(max(gi, 0), IN_W - 1);
        int gj = (int)floorf(gy); gj = min(max(gj, 0), IN_H - 1);
        t_cell = (kk >= 0 && kk < 3) ? (kk * HW + gj * IN_W + gi) : -1;
        t_mmx = gx - gw * 0.5f;  t_mmy = gx + gw * 0.5f;
        t_mmz = gy - gh * 0.5f;  t_mmw = gy + gh * 0.5f;
        t_area = gw * gh;
        t_cls = (int)tp[4];
    }

    // ---- decode 4 cells ----
    float pnx[4], pxx[4], pny[4], pxy[4], pa[4], cr[4];
    {
        const float aw = c_anchors[2 * (m0 + k)]     * 0.125f;
        const float ah = c_anchors[2 * (m0 + k) + 1] * 0.125f;
        const float xr[4] = {xv.x, xv.y, xv.z, xv.w};
        const float yr[4] = {yv.x, yv.y, yv.z, yv.w};
        const float wr[4] = {wv.x, wv.y, wv.z, wv.w};
        const float hr[4] = {hv.x, hv.y, hv.z, hv.w};
        cr[0] = cv.x; cr[1] = cv.y; cr[2] = cv.z; cr[3] = cv.w;
        #pragma unroll
        for (int c = 0; c < 4; c++) {
            float px = (float)(i0 + c) + fsig(xr[c]);
            float py = (float)j        + fsig(yr[c]);
            float pw = __expf(wr[c]) * aw;
            float ph = __expf(hr[c]) * ah;
            pnx[c] = px - pw * 0.5f;  pxx[c] = px + pw * 0.5f;
            pny[c] = py - ph * 0.5f;  pxy[c] = py + ph * 0.5f;
            pa[c]  = pw * ph;
        }
    }

    // ---- per-warp bounds via butterflies ----
    float pamin = 1e30f, pamax = -1e30f, pnymin = 1e30f, pxymax = -1e30f;
    if (vld) {
        #pragma unroll
        for (int c = 0; c < 4; c++) {
            pamin  = fminf(pamin,  pa[c]);  pamax  = fmaxf(pamax,  pa[c]);
            pnymin = fminf(pnymin, pny[c]); pxymax = fmaxf(pxymax, pxy[c]);
        }
    }
    const float wpamin  = bfly_min(pamin);
    const float wpamax  = bfly_max(pamax);
    const float wpnymin = bfly_min(pnymin);
    const float wpxymax = bfly_max(pxymax);

    // ---- per-warp prune (each lane tests its own target) ----
    unsigned keepmsk;
    {
        bool keep = false;
        if (lane < NT) {
            // trigger 3*inter-ar > pa needs ar/2 < pa < 2*ar (margined) and y-overlap
            keep = (wpamin < 2.0002f * t_area) && (2.0002f * wpamax > t_area)
                && (t_mmw >= wpnymin) && (t_mmz <= wpxymax);
        }
        keepmsk = __ballot_sync(0xffffffffu, keep);
    }

    // ---- ignore loop over survivors (shfl broadcasts; full-mask, converged) ----
    float ignmax[4] = {-1e30f, -1e30f, -1e30f, -1e30f};
    {
        unsigned msk = keepmsk;
        while (msk) {
            const int t = __ffs(msk) - 1;
            msk &= msk - 1;
            const float mmx = __shfl_sync(0xffffffffu, t_mmx, t);
            const float mmy = __shfl_sync(0xffffffffu, t_mmy, t);
            const float mmz = __shfl_sync(0xffffffffu, t_mmz, t);
            const float mmw = __shfl_sync(0xffffffffu, t_mmw, t);
            const float ar  = __shfl_sync(0xffffffffu, t_area, t);
            #pragma unroll
            for (int c = 0; c < 4; c++) {
                float iw = fminf(mmy, pxx[c]) - fmaxf(mmx, pnx[c]);
                float ih = fminf(mmw, pxy[c]) - fmaxf(mmz, pny[c]);
                float inter = fmaxf(iw, 0.f) * fmaxf(ih, 0.f);
                ignmax[c] = fmaxf(ignmax[c], fmaf(3.0f, inter, -ar));
            }
        }
    }

    // ---- obj match: ballot lanes whose target cell is in this warp's 128 cells ----
    int tm[4] = {-1, -1, -1, -1};
    {
        const int wlo = base + (tid & ~31) * 4;        // warp's first cell
        bool hit = (lane < NT) && ((unsigned)(t_cell - wlo) < 128u);
        unsigned mmsk = __ballot_sync(0xffffffffu, hit);
        while (mmsk) {                                  // ascending t: last match wins
            const int t = __ffs(mmsk) - 1;
            mmsk &= mmsk - 1;
            const int d = __shfl_sync(0xffffffffu, t_cell, t) - m4;
            #pragma unroll
            for (int c = 0; c < 4; c++) if (d == c) tm[c] = t;
        }
    }

    float objf = 0.f, loc = 0.f, clsl = 0.f, confn = 0.f, cmask = 0.f;
    const float vf = vld ? 1.0f : 0.0f;

    // conf BCE + obj count (invalid lanes contribute 0 via vf)
    #pragma unroll
    for (int c = 0; c < 4; c++) {
        const bool isobj = (tm[c] >= 0);
        objf += isobj ? 1.0f : 0.0f;
        float cm = (isobj || ignmax[c] <= pa[c]) ? vf : 0.0f;
        confn += cm * fsoftplus(isobj ? -cr[c] : cr[c]);
        cmask += cm;
    }

    // ---- rare obj path: CIoU (warp-uniform guard; LOGICAL or of sentinels!) ----
    const bool anyobj = (tm[0] >= 0) || (tm[1] >= 0) || (tm[2] >= 0) || (tm[3] >= 0);
    const unsigned objwmsk = __ballot_sync(0xffffffffu, anyobj);
    if (objwmsk) {
        #pragma unroll
        for (int c = 0; c < 4; c++) {
            const int src = (tm[c] >= 0) ? tm[c] : 0;
            const float g_minx = __shfl_sync(0xffffffffu, t_mmx, src);
            const float g_maxx = __shfl_sync(0xffffffffu, t_mmy, src);
            const float g_miny = __shfl_sync(0xffffffffu, t_mmz, src);
            const float g_maxy = __shfl_sync(0xffffffffu, t_mmw, src);
            if (tm[c] >= 0) {
                float pwc = pxx[c] - pnx[c];
                float phc = pxy[c] - pny[c];
                float px = 0.5f * (pnx[c] + pxx[c]);
                float py = 0.5f * (pny[c] + pxy[c]);
                float gw = g_maxx - g_minx, gh = g_maxy - g_miny;
                float gx = 0.5f * (g_minx + g_maxx), gy = 0.5f * (g_miny + g_maxy);
                float iw = fmaxf(fminf(g_maxx, pxx[c]) - fmaxf(g_minx, pnx[c]), 0.f);
                float ih = fmaxf(fminf(g_maxy, pxy[c]) - fmaxf(g_miny, pny[c]), 0.f);
                float inter = iw * ih;
                float uni   = fmaxf(pa[c] + gw * gh - inter, 1e-6f);
                float iou   = inter / uni;
                float dx = px - gx, dy = py - gy;
                float cd = dx * dx + dy * dy;
                float ew = fmaxf(fmaxf(g_maxx, pxx[c]) - fminf(g_minx, pnx[c]), 0.f);
                float eh = fmaxf(fmaxf(g_maxy, pxy[c]) - fminf(g_miny, pny[c]), 0.f);
                float ed = fmaxf(ew * ew + eh * eh, 1e-6f);
                float da = atanf(pwc / fmaxf(phc, 1e-6f))
                         - atanf(gw / fmaxf(gh, 1e-6f));
                float v  = 0.405284734569351f * da * da;  // 4/pi^2
                float alpha = v / fmaxf(1.0f - iou + v, 1e-6f);
                loc += 1.0f - (iou - cd / ed - alpha * v);
            }
        }

        // warp-cooperative class BCE over obj cells (32 lanes split 80 ch)
        #pragma unroll
        for (int c = 0; c < 4; c++) {
            unsigned msk = __ballot_sync(0xffffffffu, tm[c] >= 0);
            while (msk) {
                const int src = __ffs(msk) - 1;
                msk &= msk - 1;
                const int cell = __shfl_sync(0xffffffffu, m4 + c, src);
                const int t    = __shfl_sync(0xffffffffu, tm[c], src);
                const int cc   = __shfl_sync(0xffffffffu, t_cls, t);
                const int k2   = cell / HW;
                const int rem2 = cell - k2 * HW;
                const size_t off = ((size_t)b * 255 + (size_t)k2 * 85) * HW + rem2;
                float cs = 0.0f;
                #pragma unroll
                for (int q = 0; q < 3; q++) {
                    int ch = lane + q * 32;
                    if (ch < NCLS) {
                        float z = inp[off + (size_t)(5 + ch) * HW];
                        cs += fsoftplus((ch == cc) ? -z : z);
                    }
                }
                cs = warp_sum(cs);
                if (lane == 0) clsl += cs;
            }
        }
    }

    // ---- race-free block reduction: per-warp exclusive slots ----
    {
        float vals[5] = {objf, loc, clsl, confn, cmask};
        #pragma unroll
        for (int q = 0; q < 5; q++) vals[q] = warp_sum(vals[q]);
        if (lane == 0) {
            #pragma unroll
            for (int q = 0; q < 5; q++) s_wsum[wid][q] = vals[q];
        }
    }
    __syncthreads();   // the ONLY pre-finalize barrier

    const int nblocks = gridDim.x * gridDim.y;
    const int bid = blockIdx.y * gridDim.x + blockIdx.x;
    if (tid < 5) {
        double s = 0.0;
        #pragma unroll
        for (int w = 0; w < NWARP; w++) s += (double)s_wsum[w][tid];
        g_part[bid][tid] = s;
    }

    if (tid == 0) {
        __threadfence();
        unsigned v = atomicAdd(&g_count, 1u);
        s_islast = (v == (unsigned)(nblocks - 1));
        if (s_islast) g_count = 0;    // self-reset -> graph-replay deterministic
    }
    __syncthreads();
    if (!s_islast) return;

    double acc[5] = {0, 0, 0, 0, 0};
    for (int r = tid; r < nblocks; r += blockDim.x) {
        #pragma unroll
        for (int q = 0; q < 5; q++) acc[q] += g_part[r][q];
    }
    __shared__ double s_fin[5];
    if (tid < 5) s_fin[tid] = 0.0;
    __syncthreads();
    #pragma unroll
    for (int q = 0; q < 5; q++) {
        double v = warp_sumd(acc[q]);
        if (lane == 0 && v != 0.0) atomicAdd(&s_fin[q], v);
    }
    __syncthreads();
    if (tid == 0) {
        double n_obj = s_fin[0] < 1.0 ? 1.0 : s_fin[0];
        double cms   = s_fin[4] < 1.0 ? 1.0 : s_fin[4];
        const double balance = (l == 0) ? 0.4 : (l == 1 ? 1.0 : 4.0);
        const double obj_ratio = 5.0 * 608.0 * 608.0 / (416.0 * 416.0);
        double loss = s_fin[1] / n_obj * 0.05
                    + s_fin[3] / cms * balance * obj_ratio
                    + s_fin[2] / (n_obj * (double)NCLS);
        out[0] = (float)loss;
    }
}

extern "C" void kernel_launch(void* const* d_in, const int* in_sizes, int n_in,
                              void* d_out, int out_size)
{
    const float* inp  = (const float*)d_in[0];
    const float* tgt  = (const float*)d_in[1];
    const int*   lptr = (const int*)d_in[2];
    float* out = (float*)d_out;

    const int bs = in_sizes[0] / (255 * HW);        // 32
    const int blocks_x = (3 * HW / 4 + 255) / 256;  // 17

    yolo_fused<<<dim3(blocks_x, bs), 256>>>(inp, tgt, lptr, out);
}

// round 15
// speedup vs baseline: 1.6078x; 1.2917x over previous
#include <cuda_runtime.h>
#include <math.h>

// YoloLoss, fixed shape: input [32,255,76,76] f32, targets [32,20,5] f32, l int32.
// R15 = R14 with a lean finalize: per-block sums go straight into global double
// accumulators via atomicAdd (5 per block); last block just reads 5 doubles,
// computes the loss, writes out, and resets accumulators (runs alone -> safe,
// replay-deterministic). Removes the 544-row g_part scan from the serial tail.

#define IN_H 76
#define IN_W 76
#define HW   (IN_H * IN_W)        // 5776
#define NT   20
#define NCLS 80
#define NWARP 8

// global accumulators: 0=n_obj, 1=loc_sum, 2=cls_sum, 3=conf_num, 4=conf_mask_sum
__device__ double g_sum[5];          // zero-initialized at load; reset by last block
__device__ unsigned g_count = 0;

__constant__ float c_anchors[18] = {12,16, 19,36, 40,28, 36,75, 76,55,
                                    72,146, 142,110, 192,243, 459,401};

__device__ __forceinline__ float warp_sum(float v) {
    #pragma unroll
    for (int o = 16; o; o >>= 1) v += __shfl_down_sync(0xffffffffu, v, o);
    return v;
}
__device__ __forceinline__ float bfly_min(float v) {
    #pragma unroll
    for (int o = 16; o; o >>= 1) v = fminf(v, __shfl_xor_sync(0xffffffffu, v, o));
    return v;
}
__device__ __forceinline__ float bfly_max(float v) {
    #pragma unroll
    for (int o = 16; o; o >>= 1) v = fmaxf(v, __shfl_xor_sync(0xffffffffu, v, o));
    return v;
}
__device__ __forceinline__ float ftanh(float x) {
    float r;
    asm("tanh.approx.f32 %0, %1;" : "=f"(r) : "f"(x));
    return r;
}
__device__ __forceinline__ float fsig(float x) {      // 1 MUFU sigmoid
    return fmaf(0.5f, ftanh(0.5f * x), 0.5f);
}
// softplus(z) = -log(sigmoid(-z)); equals clipped-BCE term exactly for |z| < ~16
__device__ __forceinline__ float fsoftplus(float z) {
    return __logf(1.0f + __expf(z));
}

__global__ void __launch_bounds__(256, 4)
yolo_fused(const float* __restrict__ inp, const float* __restrict__ tgt,
           const int* __restrict__ lptr, float* __restrict__ out)
{
    __shared__ float s_wsum[NWARP][5];   // per-warp exclusive slots (race-free)
    __shared__ int   s_islast;

    const int b    = blockIdx.y;
    const int tid  = threadIdx.x;
    const int wid  = tid >> 5;
    const int lane = tid & 31;
    const int base = blockIdx.x * 1024;

    const int m4  = base + tid * 4;              // first cell of quad
    const bool vld = (m4 < 3 * HW);
    const int k   = min(m4 / HW, 2);             // clamp for tail quads
    const int rem = m4 - k * HW;
    const int j   = min(rem / IN_W, IN_H - 1);
    const int i0  = rem - j * IN_W;
    const size_t eoff = ((size_t)b * 255 + (size_t)k * 85) * HW + rem;

    // ---- eager input loads (MLP=5, overlap target prep) ----
    float4 xv = make_float4(0,0,0,0), yv = xv, wv = xv, hv = xv, cv = xv;
    if (vld) {
        xv = *(const float4*)(inp + eoff + 0 * HW);
        yv = *(const float4*)(inp + eoff + 1 * HW);
        wv = *(const float4*)(inp + eoff + 2 * HW);
        hv = *(const float4*)(inp + eoff + 3 * HW);
        cv = *(const float4*)(inp + eoff + 4 * HW);
    }
    const int l  = __ldg(lptr);
    const int m0 = 6 - 3 * l;

    // ---- register-resident targets: lane t owns target t ----
    float t_mmx = 0.f, t_mmy = 0.f, t_mmz = 0.f, t_mmw = 0.f, t_area = 1e30f;
    int   t_cell = -1, t_cls = 0;
    if (lane < NT) {
        const float* tp = tgt + ((size_t)b * NT + lane) * 5;
        float gx = tp[0] * (float)IN_W;
        float gy = tp[1] * (float)IN_H;
        float gw = tp[2] * (float)IN_W;
        float gh = tp[3] * (float)IN_H;
        // argmax over 9 anchors, division-free: r_a > r_b <=> inter_a*uni_b > inter_b*uni_a
        float binter = 0.0f, buni = 1e-30f; int bn = 0;
        #pragma unroll
        for (int a = 0; a < 9; a++) {
            float aw = c_anchors[2*a] * 0.125f, ah = c_anchors[2*a+1] * 0.125f;
            float inter = fminf(gw, aw) * fminf(gh, ah);
            float uni   = gw * gh + aw * ah - inter;
            if (inter * buni > binter * uni) { binter = inter; buni = uni; bn = a; }
        }
        int kk = bn - m0;
        int gi = (int)floorf(gx); gi = min(max(gi, 0), IN_W - 1);
        int gj = (int)floorf(gy); gj = min(max(gj, 0), IN_H - 1);
        t_cell = (kk >= 0 && kk < 3) ? (kk * HW + gj * IN_W + gi) : -1;
        t_mmx = gx - gw * 0.5f;  t_mmy = gx + gw * 0.5f;
        t_mmz = gy - gh * 0.5f;  t_mmw = gy + gh * 0.5f;
        t_area = gw * gh;
        t_cls = (int)tp[4];
    }

    // ---- decode 4 cells ----
    float pnx[4], pxx[4], pny[4], pxy[4], pa[4], cr[4];
    {
        const float aw = c_anchors[2 * (m0 + k)]     * 0.125f;
        const float ah = c_anchors[2 * (m0 + k) + 1] * 0.125f;
        const float xr[4] = {xv.x, xv.y, xv.z, xv.w};
        const float yr[4] = {yv.x, yv.y, yv.z, yv.w};
        const float wr[4] = {wv.x, wv.y, wv.z, wv.w};
        const float hr[4] = {hv.x, hv.y, hv.z, hv.w};
        cr[0] = cv.x; cr[1] = cv.y; cr[2] = cv.z; cr[3] = cv.w;
        #pragma unroll
        for (int c = 0; c < 4; c++) {
            float px = (float)(i0 + c) + fsig(xr[c]);
            float py = (float)j        + fsig(yr[c]);
            float pw = __expf(wr[c]) * aw;
            float ph = __expf(hr[c]) * ah;
            pnx[c] = px - pw * 0.5f;  pxx[c] = px + pw * 0.5f;
            pny[c] = py - ph * 0.5f;  pxy[c] = py + ph * 0.5f;
            pa[c]  = pw * ph;
        }
    }

    // ---- per-warp bounds via butterflies ----
    float pamin = 1e30f, pamax = -1e30f, pnymin = 1e30f, pxymax = -1e30f;
    if (vld) {
        #pragma unroll
        for (int c = 0; c < 4; c++) {
            pamin  = fminf(pamin,  pa[c]);  pamax  = fmaxf(pamax,  pa[c]);
            pnymin = fminf(pnymin, pny[c]); pxymax = fmaxf(pxymax, pxy[c]);
        }
    }
    const float wpamin  = bfly_min(pamin);
    const float wpamax  = bfly_max(pamax);
    const float wpnymin = bfly_min(pnymin);
    const float wpxymax = bfly_max(pxymax);

    // ---- per-warp prune (each lane tests its own target) ----
    unsigned keepmsk;
    {
        bool keep = false;
        if (lane < NT) {
            // trigger 3*inter-ar > pa needs ar/2 < pa < 2*ar (margined) and y-overlap
            keep = (wpamin < 2.0002f * t_area) && (2.0002f * wpamax > t_area)
                && (t_mmw >= wpnymin) && (t_mmz <= wpxymax);
        }
        keepmsk = __ballot_sync(0xffffffffu, keep);
    }

    // ---- ignore loop over survivors (shfl broadcasts; full-mask, converged) ----
    float ignmax[4] = {-1e30f, -1e30f, -1e30f, -1e30f};
    {
        unsigned msk = keepmsk;
        while (msk) {
            const int t = __ffs(msk) - 1;
            msk &= msk - 1;
            const float mmx = __shfl_sync(0xffffffffu, t_mmx, t);
            const float mmy = __shfl_sync(0xffffffffu, t_mmy, t);
            const float mmz = __shfl_sync(0xffffffffu, t_mmz, t);
            const float mmw = __shfl_sync(0xffffffffu, t_mmw, t);
            const float ar  = __shfl_sync(0xffffffffu, t_area, t);
            #pragma unroll
            for (int c = 0; c < 4; c++) {
                float iw = fminf(mmy, pxx[c]) - fmaxf(mmx, pnx[c]);
                float ih = fminf(mmw, pxy[c]) - fmaxf(mmz, pny[c]);
                float inter = fmaxf(iw, 0.f) * fmaxf(ih, 0.f);
                ignmax[c] = fmaxf(ignmax[c], fmaf(3.0f, inter, -ar));
            }
        }
    }

    // ---- obj match: ballot lanes whose target cell is in this warp's 128 cells ----
    int tm[4] = {-1, -1, -1, -1};
    {
        const int wlo = base + (tid & ~31) * 4;        // warp's first cell
        bool hit = (lane < NT) && ((unsigned)(t_cell - wlo) < 128u);
        unsigned mmsk = __ballot_sync(0xffffffffu, hit);
        while (mmsk) {                                  // ascending t: last match wins
            const int t = __ffs(mmsk) - 1;
            mmsk &= mmsk - 1;
            const int d = __shfl_sync(0xffffffffu, t_cell, t) - m4;
            #pragma unroll
            for (int c = 0; c < 4; c++) if (d == c) tm[c] = t;
        }
    }

    float objf = 0.f, loc = 0.f, clsl = 0.f, confn = 0.f, cmask = 0.f;
    const float vf = vld ? 1.0f : 0.0f;

    // conf BCE + obj count (invalid lanes contribute 0 via vf)
    #pragma unroll
    for (int c = 0; c < 4; c++) {
        const bool isobj = (tm[c] >= 0);
        objf += isobj ? 1.0f : 0.0f;
        float cm = (isobj || ignmax[c] <= pa[c]) ? vf : 0.0f;
        confn += cm * fsoftplus(isobj ? -cr[c] : cr[c]);
        cmask += cm;
    }

    // ---- rare obj path: CIoU (warp-uniform guard; logical OR of sentinels) ----
    const bool anyobj = (tm[0] >= 0) || (tm[1] >= 0) || (tm[2] >= 0) || (tm[3] >= 0);
    const unsigned objwmsk = __ballot_sync(0xffffffffu, anyobj);
    if (objwmsk) {
        #pragma unroll
        for (int c = 0; c < 4; c++) {
            const int src = (tm[c] >= 0) ? tm[c] : 0;
            const float g_minx = __shfl_sync(0xffffffffu, t_mmx, src);
            const float g_maxx = __shfl_sync(0xffffffffu, t_mmy, src);
            const float g_miny = __shfl_sync(0xffffffffu, t_mmz, src);
            const float g_maxy = __shfl_sync(0xffffffffu, t_mmw, src);
            if (tm[c] >= 0) {
                float pwc = pxx[c] - pnx[c];
                float phc = pxy[c] - pny[c];
                float px = 0.5f * (pnx[c] + pxx[c]);
                float py = 0.5f * (pny[c] + pxy[c]);
                float gw = g_maxx - g_minx, gh = g_maxy - g_miny;
                float gx = 0.5f * (g_minx + g_maxx), gy = 0.5f * (g_miny + g_maxy);
                float iw = fmaxf(fminf(g_maxx, pxx[c]) - fmaxf(g_minx, pnx[c]), 0.f);
                float ih = fmaxf(fminf(g_maxy, pxy[c]) - fmaxf(g_miny, pny[c]), 0.f);
                float inter = iw * ih;
                float uni   = fmaxf(pa[c] + gw * gh - inter, 1e-6f);
                float iou   = inter / uni;
                float dx = px - gx, dy = py - gy;
                float cd = dx * dx + dy * dy;
                float ew = fmaxf(fmaxf(g_maxx, pxx[c]) - fminf(g_minx, pnx[c]), 0.f);
                float eh = fmaxf(fmaxf(g_maxy, pxy[c]) - fminf(g_miny, pny[c]), 0.f);
                float ed = fmaxf(ew * ew + eh * eh, 1e-6f);
                float da = atanf(pwc / fmaxf(phc, 1e-6f))
                         - atanf(gw / fmaxf(gh, 1e-6f));
                float v  = 0.405284734569351f * da * da;  // 4/pi^2
                float alpha = v / fmaxf(1.0f - iou + v, 1e-6f);
                loc += 1.0f - (iou - cd / ed - alpha * v);
            }
        }

        // warp-cooperative class BCE over obj cells (32 lanes split 80 ch)
        #pragma unroll
        for (int c = 0; c < 4; c++) {
            unsigned msk = __ballot_sync(0xffffffffu, tm[c] >= 0);
            while (msk) {
                const int src = __ffs(msk) - 1;
                msk &= msk - 1;
                const int cell = __shfl_sync(0xffffffffu, m4 + c, src);
                const int t    = __shfl_sync(0xffffffffu, tm[c], src);
                const int cc   = __shfl_sync(0xffffffffu, t_cls, t);
                const int k2   = cell / HW;
                const int rem2 = cell - k2 * HW;
                const size_t off = ((size_t)b * 255 + (size_t)k2 * 85) * HW + rem2;
                float cs = 0.0f;
                #pragma unroll
                for (int q = 0; q < 3; q++) {
                    int ch = lane + q * 32;
                    if (ch < NCLS) {
                        float z = inp[off + (size_t)(5 + ch) * HW];
                        cs += fsoftplus((ch == cc) ? -z : z);
                    }
                }
                cs = warp_sum(cs);
                if (lane == 0) clsl += cs;
            }
        }
    }

    // ---- race-free block reduction: per-warp exclusive slots ----
    {
        float vals[5] = {objf, loc, clsl, confn, cmask};
        #pragma unroll
        for (int q = 0; q < 5; q++) vals[q] = warp_sum(vals[q]);
        if (lane == 0) {
            #pragma unroll
            for (int q = 0; q < 5; q++) s_wsum[wid][q] = vals[q];
        }
    }
    __syncthreads();   // the ONLY pre-finalize barrier

    // ---- direct global accumulation (5 double atomics per block) ----
    if (tid < 5) {
        double s = 0.0;
        #pragma unroll
        for (int w = 0; w < NWARP; w++) s += (double)s_wsum[w][tid];
        atomicAdd(&g_sum[tid], s);
    }

    const int nblocks = gridDim.x * gridDim.y;
    if (tid == 0) {
        __threadfence();
        unsigned v = atomicAdd(&g_count, 1u);
        s_islast = (v == (unsigned)(nblocks - 1));
    }
    __syncthreads();
    if (!s_islast) return;

    // ---- last block finalizes: read 5 doubles, compute, reset (runs alone) ----
    if (tid == 0) {
        __threadfence();
        double sn = g_sum[0], sl = g_sum[1], sc = g_sum[2], sq = g_sum[3], sm = g_sum[4];
        double n_obj = sn < 1.0 ? 1.0 : sn;
        double cms   = sm < 1.0 ? 1.0 : sm;
        const double balance = (l == 0) ? 0.4 : (l == 1 ? 1.0 : 4.0);
        const double obj_ratio = 5.0 * 608.0 * 608.0 / (416.0 * 416.0);
        double loss = sl / n_obj * 0.05
                    + sq / cms * balance * obj_ratio
                    + sc / (n_obj * (double)NCLS);
        out[0] = (float)loss;
        // reset for next graph replay (no other block is running now)
        g_sum[0] = 0.0; g_sum[1] = 0.0; g_sum[2] = 0.0; g_sum[3] = 0.0; g_sum[4] = 0.0;
        g_count = 0u;
    }
}

extern "C" void kernel_launch(void* const* d_in, const int* in_sizes, int n_in,
                              void* d_out, int out_size)
{
    const float* inp  = (const float*)d_in[0];
    const float* tgt  = (const float*)d_in[1];
    const int*   lptr = (const int*)d_in[2];
    float* out = (float*)d_out;

    const int bs = in_sizes[0] / (255 * HW);        // 32
    const int blocks_x = (3 * HW / 4 + 255) / 256;  // 17

    yolo_fused<<<dim3(blocks_x, bs), 256>>>(inp, tgt, lptr, out);
}